// round 1
// baseline (speedup 1.0000x reference)
#include <cuda_runtime.h>
#include <math_constants.h>

// Problem constants (fixed shapes from the reference)
#define NN 100000
#define EE 3200000
#define GG 256
#define HH 16

// Scratch: __device__ globals (no allocations allowed in kernel_launch)
__device__ float d_deg1[NN];
__device__ float d_deg2[NN];
__device__ float d_dis1[NN];
__device__ float d_dis2[NN];
__device__ __align__(16) float d_h1pre[NN * HH];
__device__ __align__(16) float d_acc1[NN * HH];   // becomes h1 (GCN1 output)
__device__ __align__(16) float d_out2[NN * HH];   // neighbor max-pool result
__device__ __align__(16) float d_h2pre[NN * HH];
__device__ __align__(16) float d_acc3[NN * HH];   // GCN2 output
__device__ float d_gmax[GG * HH];

__device__ __forceinline__ void red_add_v4(float* addr, float a, float b, float c, float d) {
#if __CUDA_ARCH__ >= 900
    asm volatile("red.global.add.v4.f32 [%0], {%1, %2, %3, %4};"
                 :: "l"(addr), "f"(a), "f"(b), "f"(c), "f"(d)
                 : "memory");
#else
    atomicAdd(addr + 0, a);
    atomicAdd(addr + 1, b);
    atomicAdd(addr + 2, c);
    atomicAdd(addr + 3, d);
#endif
}

// Float atomic max via native integer RED ops (no CAS loop).
__device__ __forceinline__ void atomic_max_float(float* addr, float v) {
    if (v >= 0.0f) {
        atomicMax((int*)addr, __float_as_int(v));
    } else {
        atomicMin((unsigned int*)addr, __float_as_uint(v));
    }
}

// ---------------------------------------------------------------------------
// Kernels
// ---------------------------------------------------------------------------

__global__ void k_init() {
    int t = blockIdx.x * blockDim.x + threadIdx.x;
    if (t < NN) {
        d_deg1[t] = 0.0f;
        d_deg2[t] = 0.0f;
    }
    if (t < GG * HH) d_gmax[t] = -CUDART_INF_F;
}

__global__ void k_degrees(const int* __restrict__ col, const float* __restrict__ w) {
    int e = blockIdx.x * blockDim.x + threadIdx.x;
    if (e >= EE) return;
    int c = col[e];
    atomicAdd(&d_deg1[c], w[e]);
    atomicAdd(&d_deg2[c], 1.0f);
}

// Per (node, feature): h1pre = x @ W1; acc1 = self-loop + bias; store dis1/dis2.
__global__ void k_pre1(const float* __restrict__ x, const float* __restrict__ W1,
                       const float* __restrict__ b1) {
    __shared__ float sW[7 * 16];
    __shared__ float sb[16];
    if (threadIdx.x < 7 * 16) sW[threadIdx.x] = W1[threadIdx.x];
    if (threadIdx.x < 16) sb[threadIdx.x] = b1[threadIdx.x];
    __syncthreads();
    int t = blockIdx.x * blockDim.x + threadIdx.x;
    if (t >= NN * HH) return;
    int i = t >> 4, f = t & 15;
    float di1 = rsqrtf(d_deg1[i] + 1.0f);  // +1 for self loop
    float di2 = rsqrtf(d_deg2[i] + 1.0f);
    if (f == 0) { d_dis1[i] = di1; d_dis2[i] = di2; }
    float s = 0.0f;
#pragma unroll
    for (int k = 0; k < 7; k++) s += x[i * 7 + k] * sW[k * 16 + f];
    d_h1pre[t] = s;
    d_acc1[t] = di1 * di1 * s + sb[f];  // self-loop contribution + bias
}

// GCN1 edge scatter: acc1[col] += dis1[row]*w*dis1[col] * h1pre[row]
__global__ void k_gcn1(const int* __restrict__ row, const int* __restrict__ col,
                       const float* __restrict__ w) {
    int t = blockIdx.x * blockDim.x + threadIdx.x;
    if (t >= EE * 4) return;
    int e = t >> 2, q = (t & 3) << 2;
    int r = row[e], c = col[e];
    float nrm = d_dis1[r] * w[e] * d_dis1[c];
    const float4 h = *reinterpret_cast<const float4*>(&d_h1pre[r * HH + q]);
    red_add_v4(&d_acc1[c * HH + q], h.x * nrm, h.y * nrm, h.z * nrm, h.w * nrm);
}

// out2 = acc1 (self-loop identity for neighbor max pool)
__global__ void k_copy() {
    int t = blockIdx.x * blockDim.x + threadIdx.x;
    if (t >= NN * HH / 4) return;
    reinterpret_cast<float4*>(d_out2)[t] = reinterpret_cast<const float4*>(d_acc1)[t];
}

// out2[col] = max(out2[col], h1[row]) over edges
__global__ void k_maxpool(const int* __restrict__ row, const int* __restrict__ col) {
    int t = blockIdx.x * blockDim.x + threadIdx.x;
    if (t >= EE * 4) return;
    int e = t >> 2, q = (t & 3) << 2;
    int r = row[e], c = col[e];
    const float4 h = *reinterpret_cast<const float4*>(&d_acc1[r * HH + q]);
    float* dst = &d_out2[c * HH + q];
    atomic_max_float(dst + 0, h.x);
    atomic_max_float(dst + 1, h.y);
    atomic_max_float(dst + 2, h.z);
    atomic_max_float(dst + 3, h.w);
}

// Per (node, feature): h2pre = out2 @ W2; acc3 = self-loop + bias.
__global__ void k_pre2(const float* __restrict__ W2, const float* __restrict__ b2) {
    __shared__ float sW[16 * 16];
    __shared__ float sb[16];
    if (threadIdx.x < 256) sW[threadIdx.x] = W2[threadIdx.x];
    if (threadIdx.x < 16) sb[threadIdx.x] = b2[threadIdx.x];
    __syncthreads();
    int t = blockIdx.x * blockDim.x + threadIdx.x;
    if (t >= NN * HH) return;
    int i = t >> 4, f = t & 15;
    const float* hrow = &d_out2[i * HH];
    float s = 0.0f;
#pragma unroll
    for (int k = 0; k < 16; k++) s += hrow[k] * sW[k * 16 + f];
    d_h2pre[t] = s;
    float di2 = d_dis2[i];
    d_acc3[t] = di2 * di2 * s + sb[f];
}

// GCN2 edge scatter (edge weights = 1): acc3[col] += dis2[r]*dis2[c]*h2pre[r]
__global__ void k_gcn2(const int* __restrict__ row, const int* __restrict__ col) {
    int t = blockIdx.x * blockDim.x + threadIdx.x;
    if (t >= EE * 4) return;
    int e = t >> 2, q = (t & 3) << 2;
    int r = row[e], c = col[e];
    float nrm = d_dis2[r] * d_dis2[c];
    const float4 h = *reinterpret_cast<const float4*>(&d_h2pre[r * HH + q]);
    red_add_v4(&d_acc3[c * HH + q], h.x * nrm, h.y * nrm, h.z * nrm, h.w * nrm);
}

// h = relu(out2 + acc3); gmax[batch[i]] = max over nodes
__global__ void k_relu_gmax(const int* __restrict__ batch) {
    int t = blockIdx.x * blockDim.x + threadIdx.x;
    if (t >= NN * HH) return;
    int i = t >> 4, f = t & 15;
    float h = fmaxf(d_out2[t] + d_acc3[t], 0.0f);
    atomic_max_float(&d_gmax[batch[i] * HH + f], h);
}

// Tiny residual MLP on [G, H]: one thread per graph.
__global__ void k_mlp(const float* __restrict__ Wl1, const float* __restrict__ bl1,
                      const float* __restrict__ Wl3, const float* __restrict__ bl3,
                      const float* __restrict__ Wl4, const float* __restrict__ bl4,
                      float* __restrict__ out) {
    __shared__ float s1[256], s3[256], s4[16], sb1[16], sb3[16];
    __shared__ float sb4;
    int tx = threadIdx.x;
    s1[tx] = Wl1[tx];
    s3[tx] = Wl3[tx];
    if (tx < 16) { s4[tx] = Wl4[tx]; sb1[tx] = bl1[tx]; sb3[tx] = bl3[tx]; }
    if (tx == 0) sb4 = bl4[0];
    __syncthreads();

    const float SLOPE = 0.22916666666666666f;  // eval-mode RReLU mean slope
    float v[16], u[16];
#pragma unroll
    for (int f = 0; f < 16; f++) v[f] = d_gmax[tx * 16 + f];
#pragma unroll
    for (int f = 0; f < 16; f++) {
        float s = sb1[f] + v[f];
#pragma unroll
        for (int k = 0; k < 16; k++) s += v[k] * s1[k * 16 + f];
        u[f] = (s >= 0.0f) ? s : SLOPE * s;
    }
#pragma unroll
    for (int f = 0; f < 16; f++) {
        float s = sb3[f] + u[f];
#pragma unroll
        for (int k = 0; k < 16; k++) s += u[k] * s3[k * 16 + f];
        v[f] = (s >= 0.0f) ? s : SLOPE * s;
    }
    float s = sb4;
#pragma unroll
    for (int k = 0; k < 16; k++) s += v[k] * s4[k];
    out[tx] = (s >= 0.0f) ? s : SLOPE * s;
}

// ---------------------------------------------------------------------------
// Launch
// ---------------------------------------------------------------------------

extern "C" void kernel_launch(void* const* d_in, const int* in_sizes, int n_in,
                              void* d_out, int out_size) {
    const float* x    = (const float*)d_in[0];
    const int*   ei   = (const int*)d_in[1];
    const int*   batch= (const int*)d_in[2];
    const float* ew   = (const float*)d_in[3];
    const float* W1   = (const float*)d_in[4];
    const float* b1   = (const float*)d_in[5];
    const float* W2   = (const float*)d_in[6];
    const float* b2   = (const float*)d_in[7];
    const float* Wl1  = (const float*)d_in[8];
    const float* bl1  = (const float*)d_in[9];
    const float* Wl3  = (const float*)d_in[10];
    const float* bl3  = (const float*)d_in[11];
    const float* Wl4  = (const float*)d_in[12];
    const float* bl4  = (const float*)d_in[13];
    const int* row = ei;         // edge_index[0]
    const int* col = ei + EE;    // edge_index[1]
    float* out = (float*)d_out;

    const int T = 256;
    k_init<<<(NN + T - 1) / T, T>>>();
    k_degrees<<<(EE + T - 1) / T, T>>>(col, ew);
    k_pre1<<<(NN * HH + T - 1) / T, T>>>(x, W1, b1);
    k_gcn1<<<(EE * 4 + T - 1) / T, T>>>(row, col, ew);
    k_copy<<<(NN * HH / 4 + T - 1) / T, T>>>();
    k_maxpool<<<(EE * 4 + T - 1) / T, T>>>(row, col);
    k_pre2<<<(NN * HH + T - 1) / T, T>>>(W2, b2);
    k_gcn2<<<(EE * 4 + T - 1) / T, T>>>(row, col);
    k_relu_gmax<<<(NN * HH + T - 1) / T, T>>>(batch);
    k_mlp<<<1, 256>>>(Wl1, bl1, Wl3, bl3, Wl4, bl4, out);
}